// round 2
// baseline (speedup 1.0000x reference)
#include <cuda_runtime.h>
#include <math.h>

// Problem constants
#define HH      112
#define WW      112
#define L_TOT   (HH * WW)        // 12544
#define C_IN    64
#define C_OUT   64
#define K_TOT   (C_IN * 9)       // 576
#define M_TILE  64
#define K_CHUNK 16

__device__ float g_wsum[C_OUT];

// Row sums S[o] = sum_k W[o,k]
__global__ void rowsum_kernel(const float* __restrict__ w) {
    int o = threadIdx.x;
    if (o >= C_OUT) return;
    float s = 0.f;
    #pragma unroll 8
    for (int k = 0; k < K_TOT; ++k) s += w[o * K_TOT + k];
    g_wsum[o] = s;
}

__device__ __forceinline__ float sigm(float x) {
    return 1.f / (1.f + expf(-x));
}

// Implicit-GEMM conv computing C1=conv(u), C2=conv(u^2), C3=conv(u^3)
// simultaneously (shared B tile), then fused epilogue.
// Block: 64 spatial positions (m) x 64 output channels (n), 256 threads,
// each thread owns a 4m x 4n micro-tile with 3 accumulators each.
__global__ __launch_bounds__(256) void conv_poly_kernel(
    const float* __restrict__ img,
    const float* __restrict__ wts,
    float* __restrict__ out)
{
    __shared__ float As1[K_CHUNK][M_TILE];
    __shared__ float As2[K_CHUNK][M_TILE];
    __shared__ float As3[K_CHUNK][M_TILE];
    __shared__ float Bs [K_CHUNK][C_OUT];

    const int tid    = threadIdx.x;
    const int tx     = tid & 15;   // n-group: 16 x 4 = 64 output channels
    const int ty     = tid >> 4;   // m-group: 16 x 4 = 64 spatial positions
    const int b      = blockIdx.y;
    const int m_base = blockIdx.x * M_TILE;

    const float* imgb = img + (size_t)b * C_IN * L_TOT;

    float acc1[4][4] = {{0.f}}, acc2[4][4] = {{0.f}}, acc3[4][4] = {{0.f}};

    const int bo = tid >> 2;  // 0..63 output channel for B staging
    const int bq = tid & 3;   // 0..3 k-quad for B staging

    for (int k0 = 0; k0 < K_TOT; k0 += K_CHUNK) {
        // ---- stage B tile (coalesced float4 along k, transposed into smem) ----
        {
            float4 w4 = *reinterpret_cast<const float4*>(&wts[bo * K_TOT + k0 + bq * 4]);
            Bs[bq * 4 + 0][bo] = w4.x;
            Bs[bq * 4 + 1][bo] = w4.y;
            Bs[bq * 4 + 2][bo] = w4.z;
            Bs[bq * 4 + 3][bo] = w4.w;
        }
        // ---- stage A tile: u, u^2, u^3 (im2col gather, coalesced along m) ----
        #pragma unroll
        for (int i = 0; i < 4; ++i) {
            int flat = tid + i * 256;
            int m  = flat & 63;
            int kk = flat >> 6;
            int k  = k0 + kk;
            int c   = k / 9;
            int tap = k - c * 9;
            int dy  = tap / 3;
            int dx  = tap - dy * 3;
            int gm = m_base + m;
            int y  = gm / WW;
            int x  = gm - y * WW;
            int iy = y + dy - 1;
            int ix = x + dx - 1;
            float v = 0.f;
            if ((unsigned)iy < (unsigned)HH && (unsigned)ix < (unsigned)WW)
                v = imgb[c * L_TOT + iy * WW + ix];
            float v2 = v * v;
            As1[kk][m] = v;
            As2[kk][m] = v2;
            As3[kk][m] = v2 * v;
        }
        __syncthreads();

        // ---- 48 FMAs per k-step per thread ----
        #pragma unroll
        for (int kk = 0; kk < K_CHUNK; ++kk) {
            float4 a1 = *reinterpret_cast<const float4*>(&As1[kk][ty * 4]);
            float4 a2 = *reinterpret_cast<const float4*>(&As2[kk][ty * 4]);
            float4 a3 = *reinterpret_cast<const float4*>(&As3[kk][ty * 4]);
            float4 bw = *reinterpret_cast<const float4*>(&Bs [kk][tx * 4]);
            float av1[4] = {a1.x, a1.y, a1.z, a1.w};
            float av2[4] = {a2.x, a2.y, a2.z, a2.w};
            float av3[4] = {a3.x, a3.y, a3.z, a3.w};
            float bv [4] = {bw.x, bw.y, bw.z, bw.w};
            #pragma unroll
            for (int mi = 0; mi < 4; ++mi) {
                #pragma unroll
                for (int ni = 0; ni < 4; ++ni) {
                    acc1[mi][ni] += av1[mi] * bv[ni];
                    acc2[mi][ni] += av2[mi] * bv[ni];
                    acc3[mi][ni] += av3[mi] * bv[ni];
                }
            }
        }
        __syncthreads();
    }

    // ---- fused epilogue ----
    // f  = (-0.000287*S + 0.266*C1 - 0.1097*C2) / 75
    // gi = const_i + aS_i*S + a1_i*C1 + a2_i*C2 + a3_i*C3
    // out = g5 + t1(g1-g2) + t2(g2-g3) + t3(g3-g4) + t4(g4-g5),
    //       t_i = sigmoid(10*(theta_i - f)), thetas = .15 .23 .32 .39
    const int n_base = tx * 4;
    const int gm0    = m_base + ty * 4;
    const float Kf = (float)K_TOT;

    #pragma unroll
    for (int ni = 0; ni < 4; ++ni) {
        int o = n_base + ni;
        float S = g_wsum[o];
        float4 res;
        float* resp = &res.x;
        #pragma unroll
        for (int mi = 0; mi < 4; ++mi) {
            float c1 = acc1[mi][ni];
            float c2 = acc2[mi][ni];
            float c3 = acc3[mi][ni];

            float f = (-0.000287f * S + 0.266f * c1 - 0.1097f * c2) * (1.f / 75.f);

            float g1 = (0.11f  / 75.f) * Kf + 0.001309f  * S + 0.00619f   * c1 - 0.009f    * c2 + 0.001383f * c3;
            float g2 = (0.179f / 75.f) * Kf - 0.0025f    * S + 0.00303f   * c1 - 0.00484f  * c2 + 0.0175f   * c3;
            float g3 = (0.238f / 75.f) * Kf - 0.000954f  * S + 0.00187f   * c1 + 0.001877f * c2 + 0.01502f  * c3;
            float g4 = (0.388f / 75.f) * Kf - 0.00734f   * S + 0.001117f  * c1 + 0.00752f  * c2 + 0.009f    * c3;
            float g5 = (0.507f / 75.f) * Kf - 0.01017f   * S + 0.000426f  * c1 + 0.00837f  * c2 + 0.00413f  * c3;

            float t1 = sigm(10.f * (0.15f - f));
            float t2 = sigm(10.f * (0.23f - f));
            float t3 = sigm(10.f * (0.32f - f));
            float t4 = sigm(10.f * (0.39f - f));

            resp[mi] = g5 + t1 * (g1 - g2) + t2 * (g2 - g3) + t3 * (g3 - g4) + t4 * (g4 - g5);
        }
        *reinterpret_cast<float4*>(&out[((size_t)(b * C_OUT + o)) * L_TOT + gm0]) = res;
    }
}

extern "C" void kernel_launch(void* const* d_in, const int* in_sizes, int n_in,
                              void* d_out, int out_size) {
    const float* img = (const float*)d_in[0];
    const float* wts = (const float*)d_in[1];
    float* out = (float*)d_out;

    int B = in_sizes[0] / (C_IN * L_TOT);   // 8

    rowsum_kernel<<<1, 64>>>(wts);
    dim3 grid(L_TOT / M_TILE, B);
    conv_poly_kernel<<<grid, 256>>>(img, wts, out);
}

// round 4
// speedup vs baseline: 2.5509x; 2.5509x over previous
#include <cuda_runtime.h>
#include <cstdint>
#include <math.h>

#define L_TOT   12544
#define C_IN    64
#define C_OUT   64
#define K_TOT   576
#define M_TILE  128
#define KC      32
#define NCHUNK  (K_TOT / KC)   // 18

// ---- smem byte offsets (A/B tiles 1024-aligned for SW128 descriptors) ----
#define OFF_TMEM 0
#define OFF_MBAR 8
#define OFF_WSUM 16            // 64 floats
#define OFF_OFFT 512           // 576 ints
#define OFF_A1   3072          // [128][32] tf32, 16KB
#define OFF_A2   (OFF_A1 + 16384)
#define OFF_A3   (OFF_A2 + 16384)
#define OFF_B    (OFF_A3 + 16384)   // [64][32] tf32, 8KB
#define SMEM_TOTAL (OFF_B + 8192)

// idesc: dtype=F32(1<<4), atype=TF32(2<<7), btype=TF32(2<<10), N=64(8<<17), M=128(8<<24)
#define IDESC_TF32 0x8100910u

// tcgen05 only exists on the arch-specific target sm_103a; the harness also
// compiles a plain compute_103 pass which must not see these instructions.
#if defined(__CUDA_ARCH_FEAT_SM103_ALL) || \
    (defined(__CUDA_ARCH_SPECIFIC__) && (__CUDA_ARCH_SPECIFIC__ == 1030)) || \
    (defined(__CUDA_ARCH_FAMILY_SPECIFIC__) && (__CUDA_ARCH_FAMILY_SPECIFIC__ == 1030))
#define HAS_TCGEN05 1
#else
#define HAS_TCGEN05 0
#endif

__device__ float g_wsum[C_OUT];

__global__ void rowsum_kernel(const float* __restrict__ w) {
    int o = threadIdx.x;
    if (o >= C_OUT) return;
    float s = 0.f;
    #pragma unroll 8
    for (int k = 0; k < K_TOT; ++k) s += w[o * K_TOT + k];
    g_wsum[o] = s;
}

__device__ __forceinline__ float sigm(float x) { return 1.f / (1.f + __expf(-x)); }

// Shared epilogue: (S, C1, C2, C3) -> blended output
__device__ __forceinline__ float epilogue(float S, float c1, float c2, float c3) {
    const float Kf = (float)K_TOT;
    float f = (-0.000287f * S + 0.266f * c1 - 0.1097f * c2) * (1.f / 75.f);

    float g1 = (0.11f  / 75.f) * Kf + 0.001309f * S + 0.00619f  * c1 - 0.009f    * c2 + 0.001383f * c3;
    float g2 = (0.179f / 75.f) * Kf - 0.0025f   * S + 0.00303f  * c1 - 0.00484f  * c2 + 0.0175f   * c3;
    float g3 = (0.238f / 75.f) * Kf - 0.000954f * S + 0.00187f  * c1 + 0.001877f * c2 + 0.01502f  * c3;
    float g4 = (0.388f / 75.f) * Kf - 0.00734f  * S + 0.001117f * c1 + 0.00752f  * c2 + 0.009f    * c3;
    float g5 = (0.507f / 75.f) * Kf - 0.01017f  * S + 0.000426f * c1 + 0.00837f  * c2 + 0.00413f  * c3;

    float t1 = sigm(10.f * (0.15f - f));
    float t2 = sigm(10.f * (0.23f - f));
    float t3 = sigm(10.f * (0.32f - f));
    float t4 = sigm(10.f * (0.39f - f));

    return g5 + t1 * (g1 - g2) + t2 * (g2 - g3) + t3 * (g3 - g4) + t4 * (g4 - g5);
}

#if HAS_TCGEN05
// ---------------- PTX helpers (sm_103a only) ----------------
__device__ __forceinline__ uint32_t smem_u32(const void* p) {
    uint32_t a;
    asm("{ .reg .u64 t; cvta.to.shared.u64 t, %1; cvt.u32.u64 %0, t; }" : "=r"(a) : "l"(p));
    return a;
}
__device__ __forceinline__ uint32_t elect_one() {
    uint32_t p;
    asm volatile("{ .reg .pred p; elect.sync _|p, 0xFFFFFFFF; selp.b32 %0, 1, 0, p; }" : "=r"(p));
    return p;
}
__device__ __forceinline__ float tf32r(float x) {
    float y; asm("cvt.rna.tf32.f32 %0, %1;" : "=f"(y) : "f"(x)); return y;
}

#define MBARRIER_INIT(addr, cnt) \
    asm volatile("mbarrier.init.shared.b64 [%0], %1;" :: "r"((uint32_t)(addr)), "r"((uint32_t)(cnt)) : "memory")

#define MBARRIER_WAIT_PARITY(mb, par) do {                                          \
    uint32_t _mb = (uint32_t)(mb), _p = (uint32_t)(par), _d;                        \
    asm volatile("{ .reg .pred p; mbarrier.try_wait.parity.acquire.cta.shared::cta.b64 p, [%1], %2; selp.b32 %0,1,0,p; }" \
        : "=r"(_d) : "r"(_mb), "r"(_p) : "memory");                                 \
    if (!_d) {                                                                      \
        asm volatile("{ .reg .pred P1;\n\t"                                         \
            "WL_%=: mbarrier.try_wait.parity.acquire.cta.shared::cta.b64 P1, [%0], %1, 0x989680;\n\t" \
            "@P1 bra.uni WD_%=;\n\t bra.uni WL_%=;\n\t WD_%=: }"                    \
            :: "r"(_mb), "r"(_p) : "memory");                                       \
    }                                                                               \
} while (0)

#define TCGEN05_ALLOC(sm, n) \
    asm volatile("tcgen05.alloc.cta_group::1.sync.aligned.shared::cta.b32 [%0], %1;" \
        :: "r"((uint32_t)(sm)), "r"((uint32_t)(n)) : "memory")
#define TCGEN05_RELINQ() \
    asm volatile("tcgen05.relinquish_alloc_permit.cta_group::1.sync.aligned;")
#define TCGEN05_DEALLOC(t, n) \
    asm volatile("tcgen05.dealloc.cta_group::1.sync.aligned.b32 %0, %1;" :: "r"(t), "r"((uint32_t)(n)))
#define TCGEN05_COMMIT(mb) \
    asm volatile("tcgen05.commit.cta_group::1.mbarrier::arrive::one.shared::cluster.b64 [%0];" \
        :: "r"((uint32_t)(mb)) : "memory")
#define TCGEN05_WAIT_LD()  asm volatile("tcgen05.wait::ld.sync.aligned;" ::: "memory")
#define TCGEN05_FENCE_AFTER() asm volatile("tcgen05.fence::after_thread_sync;" ::: "memory")

#define TCGEN05_LD_X16(r, addr) \
    asm volatile("tcgen05.ld.sync.aligned.32x32b.x16.b32 " \
        "{%0,%1,%2,%3,%4,%5,%6,%7,%8,%9,%10,%11,%12,%13,%14,%15}, [%16];" \
        : "=r"((r)[0]),"=r"((r)[1]),"=r"((r)[2]),"=r"((r)[3]),   \
          "=r"((r)[4]),"=r"((r)[5]),"=r"((r)[6]),"=r"((r)[7]),   \
          "=r"((r)[8]),"=r"((r)[9]),"=r"((r)[10]),"=r"((r)[11]), \
          "=r"((r)[12]),"=r"((r)[13]),"=r"((r)[14]),"=r"((r)[15]) \
        : "r"(addr))

// SW128 K-major smem descriptor (layout=2, version=1, SBO=64, LBO=1)
__device__ __forceinline__ uint64_t make_desc_sw128(uint32_t addr) {
    return ((uint64_t)2 << 61) | ((uint64_t)1 << 46) | ((uint64_t)64 << 32) |
           ((uint64_t)1 << 16) | ((uint64_t)(addr >> 4) & 0x3FFF);
}

__device__ __forceinline__ void mma_tf32_ss(uint32_t d, uint64_t ad, uint64_t bd,
                                            uint32_t idesc, uint32_t en) {
    asm volatile(
        "{ .reg .pred p; setp.ne.u32 p, %4, 0;\n\t"
        "tcgen05.mma.cta_group::1.kind::tf32 [%0], %1, %2, %3, {%5,%5,%5,%5}, p; }\n"
        :: "r"(d), "l"(ad), "l"(bd), "r"(idesc), "r"(en), "r"(0u) : "memory");
}
#endif // HAS_TCGEN05

// ---------------- main kernel ----------------
__global__ __launch_bounds__(256, 2) void conv_tc_kernel(
    const float* __restrict__ img,
    const float* __restrict__ wts,
    float* __restrict__ out)
{
#if HAS_TCGEN05
    extern __shared__ char smem[];
    const uint32_t sb = smem_u32(smem);
    const int tid = threadIdx.x, wid = tid >> 5, lane = tid & 31;
    const int bx = blockIdx.x;
    const int b = bx / 98, mb = bx - b * 98;
    const int m_base = mb * M_TILE;
    const float* imgb = img + (size_t)b * C_IN * L_TOT;

    // TMEM alloc + mbar init + tables
    if (wid == 0) { TCGEN05_ALLOC(sb + OFF_TMEM, 256); TCGEN05_RELINQ(); }
    if (tid == 0) MBARRIER_INIT(sb + OFF_MBAR, 1);
    if (tid < C_OUT) ((float*)(smem + OFF_WSUM))[tid] = g_wsum[tid];
    for (int k = tid; k < K_TOT; k += 256) {
        int c = k / 9, r = k - c * 9, dy = r / 3, dx = r - dy * 3;
        ((int*)(smem + OFF_OFFT))[k] = (c * L_TOT + dy * 112 + dx) | (dy << 20) | (dx << 22);
    }
    __syncthreads();
    uint32_t tmem;
    asm volatile("ld.shared.b32 %0, [%1];" : "=r"(tmem) : "r"(sb + OFF_TMEM));

    // per-thread staging geometry: fixed m, kq in {base, base+2, base+4, base+6}
    const int m  = tid & 127;
    const int gm = m_base + m;
    const int y  = gm / 112, x = gm - y * 112;
    const int pre = (y - 1) * 112 + (x - 1);
    unsigned ymask = 0, xmask = 0;
    #pragma unroll
    for (int d = 0; d < 3; ++d) {
        if ((unsigned)(y - 1 + d) < 112u) ymask |= 1u << d;
        if ((unsigned)(x - 1 + d) < 112u) xmask |= 1u << d;
    }

    const uint64_t ad1 = make_desc_sw128(sb + OFF_A1);
    const uint64_t ad2 = make_desc_sw128(sb + OFF_A2);
    const uint64_t ad3 = make_desc_sw128(sb + OFF_A3);
    const uint64_t bd  = make_desc_sw128(sb + OFF_B);

    int ph = 0;
    for (int ch = 0; ch < NCHUNK; ++ch) {
        const int k0 = ch * KC;
        // ---- stage B (weights): 512 float4 tasks over 256 threads ----
        #pragma unroll
        for (int i = 0; i < 2; ++i) {
            int id = i * 256 + tid;
            int o = id >> 3, q = id & 7;
            float4 w4 = *(const float4*)(wts + o * K_TOT + k0 + q * 4);
            w4.x = tf32r(w4.x); w4.y = tf32r(w4.y); w4.z = tf32r(w4.z); w4.w = tf32r(w4.w);
            uint32_t bo = (uint32_t)(o * 128 + q * 16);
            bo ^= (bo >> 3) & 0x70;
            *(float4*)(smem + OFF_B + bo) = w4;
        }
        // ---- stage A (u, u^2, u^3): 1024 float4-triple tasks ----
        const int* offp = (const int*)(smem + OFF_OFFT) + k0;
        #pragma unroll
        for (int i = 0; i < 4; ++i) {
            const int kq = i * 2 + (tid >> 7);
            int4 pk = *(const int4*)(offp + kq * 4);
            float4 r1, r2, r3;
            {
                int pv[4] = {pk.x, pk.y, pk.z, pk.w};
                float* p1 = &r1.x; float* p2 = &r2.x; float* p3 = &r3.x;
                #pragma unroll
                for (int j = 0; j < 4; ++j) {
                    int p = pv[j];
                    int off = p & 0xFFFFF;
                    int dy = (p >> 20) & 3, dx = (p >> 22) & 3;
                    float v = 0.f;
                    if (((ymask >> dy) & 1u) && ((xmask >> dx) & 1u))
                        v = __ldg(imgb + off + pre);
                    float v2 = v * v;
                    p1[j] = tf32r(v);
                    p2[j] = tf32r(v2);
                    p3[j] = tf32r(v2 * v);
                }
            }
            uint32_t bo = (uint32_t)(m * 128 + kq * 16);
            bo ^= (bo >> 3) & 0x70;
            *(float4*)(smem + OFF_A1 + bo) = r1;
            *(float4*)(smem + OFF_A2 + bo) = r2;
            *(float4*)(smem + OFF_A3 + bo) = r3;
        }
        asm volatile("fence.proxy.async.shared::cta;" ::: "memory");
        __syncthreads();

        if (wid == 0 && elect_one()) {
            #pragma unroll
            for (int s = 0; s < 4; ++s) {   // 4 K-steps of 8 (32B each)
                uint32_t en = (ch > 0 || s > 0) ? 1u : 0u;
                mma_tf32_ss(tmem + 0,   ad1 + s * 2, bd + s * 2, IDESC_TF32, en);
                mma_tf32_ss(tmem + 64,  ad2 + s * 2, bd + s * 2, IDESC_TF32, en);
                mma_tf32_ss(tmem + 128, ad3 + s * 2, bd + s * 2, IDESC_TF32, en);
            }
            TCGEN05_COMMIT(sb + OFF_MBAR);
        }
        MBARRIER_WAIT_PARITY(sb + OFF_MBAR, ph);
        ph ^= 1;
    }

    // ---- fused epilogue from TMEM ----
    TCGEN05_FENCE_AFTER();
    const int msub  = wid & 3;           // TMEM subpartition (lane slice)
    const int nhalf = (wid >> 2) * 32;   // n-column half
    const float* sw = (const float*)(smem + OFF_WSUM);
    const int mg = m_base + msub * 32 + lane;

    #pragma unroll
    for (int h = 0; h < 2; ++h) {
        const int n0 = nhalf + h * 16;
        uint32_t a1[16], a2[16], a3[16];
        TCGEN05_LD_X16(a1, tmem + 0   + n0);
        TCGEN05_LD_X16(a2, tmem + 64  + n0);
        TCGEN05_LD_X16(a3, tmem + 128 + n0);
        TCGEN05_WAIT_LD();
        #pragma unroll
        for (int ni = 0; ni < 16; ++ni) {
            const int o = n0 + ni;
            float res = epilogue(sw[o],
                                 __uint_as_float(a1[ni]),
                                 __uint_as_float(a2[ni]),
                                 __uint_as_float(a3[ni]));
            out[(size_t)(b * C_OUT + o) * L_TOT + mg] = res;
        }
    }

    __syncthreads();
    if (wid == 0) TCGEN05_DEALLOC(tmem, 256);
#else
    // ---------- fallback for non-sm_103a compilation passes (never runs on GB300) ----------
    const int tid = threadIdx.x;
    const int bx = blockIdx.x;
    const int b = bx / 98, mb = bx - b * 98;
    const int m_base = mb * M_TILE;
    const float* imgb = img + (size_t)b * C_IN * L_TOT;

    for (int idx = tid; idx < M_TILE * C_OUT; idx += 256) {
        int m = idx & 127, o = idx >> 7;
        int gm = m_base + m;
        int y = gm / 112, x = gm - y * 112;
        float c1 = 0.f, c2 = 0.f, c3 = 0.f;
        for (int k = 0; k < K_TOT; ++k) {
            int c = k / 9, r = k - c * 9, dy = r / 3, dx = r - dy * 3;
            int iy = y + dy - 1, ix = x + dx - 1;
            float v = 0.f;
            if ((unsigned)iy < 112u && (unsigned)ix < 112u)
                v = imgb[c * L_TOT + iy * 112 + ix];
            float w = wts[o * K_TOT + k];
            c1 += v * w; c2 += v * v * w; c3 += v * v * v * w;
        }
        out[(size_t)(b * C_OUT + o) * L_TOT + gm] = epilogue(g_wsum[o], c1, c2, c3);
    }
#endif
}

extern "C" void kernel_launch(void* const* d_in, const int* in_sizes, int n_in,
                              void* d_out, int out_size) {
    const float* img = (const float*)d_in[0];
    const float* wts = (const float*)d_in[1];
    float* out = (float*)d_out;

    int B = in_sizes[0] / (C_IN * L_TOT);   // 8

    cudaFuncSetAttribute(conv_tc_kernel, cudaFuncAttributeMaxDynamicSharedMemorySize, SMEM_TOTAL);
    rowsum_kernel<<<1, 64>>>(wts);
    conv_tc_kernel<<<B * 98, 256, SMEM_TOTAL>>>(img, wts, out);
}